// round 8
// baseline (speedup 1.0000x reference)
#include <cuda_runtime.h>
#include <cuda_fp16.h>

// FALayer, dst-bucketed:
//   memset(deg) -> proj(+fp16 copy, +fused dst histogram) -> scanA ->
//   scanB(one warp) -> scanC(shuffle) -> scatter(x4 ILP) -> gather(16 lanes/node)
// Inputs: 0 h[N,128]f32  1 d[N]f32  2 yes_no[E]f32  3 gate_w[1,256]f32
//         4 gate_b[1]f32 5 yes_w f32 6 no_w f32  7 src[E]i32  8 dst[E]i32
// Output: z[N,128]f32

#define D 128
#define MAX_N 100352
#define MAX_E 1605632
#define SCAN_B 512
#define MAX_SCAN_BLOCKS 256

__device__ float2 g_pd2[MAX_N];            // (p_dst, d) per node
__device__ float2 g_ps2[MAX_N];            // (p_src, d) per node
__device__ int g_deg[MAX_N];
__device__ int g_offs[MAX_N + 1];
__device__ int g_cursor[MAX_N];
__device__ int g_bsum[MAX_SCAN_BLOCKS];
__device__ int g_boff[MAX_SCAN_BLOCKS];
__device__ long long g_pairs[MAX_E];                 // lo32 src, hi32 coef bits
__device__ __half2 g_h2[(size_t)MAX_N * (D / 2)];    // fp16 h copy (25.7 MB)

// -------------------------------- proj + fp16 convert + fused dst histogram
__global__ void proj_kernel(const float* __restrict__ h,
                            const float* __restrict__ dnorm,
                            const float* __restrict__ gate_w,
                            const int* __restrict__ dst,
                            int n_nodes, int n_edges) {
    int gtid = blockIdx.x * blockDim.x + threadIdx.x;

    // fused histogram (g_deg pre-zeroed by memset); grid covers all edges
    for (int e = gtid; e < n_edges; e += gridDim.x * blockDim.x)
        atomicAdd(&g_deg[dst[e]], 1);

    int warp = gtid >> 5;
    int lane = threadIdx.x & 31;
    if (warp >= n_nodes) return;

    const float4* hrow = reinterpret_cast<const float4*>(h + (size_t)warp * D);
    const float4* wd = reinterpret_cast<const float4*>(gate_w);
    const float4* ws = reinterpret_cast<const float4*>(gate_w + D);

    float4 hv = hrow[lane];
    float4 wdv = wd[lane];
    float4 wsv = ws[lane];

    __half2 a = __floats2half2_rn(hv.x, hv.y);
    __half2 b = __floats2half2_rn(hv.z, hv.w);
    size_t base = (size_t)warp * (D / 2) + lane * 2;
    g_h2[base] = a;
    g_h2[base + 1] = b;

    float pd = hv.x * wdv.x + hv.y * wdv.y + hv.z * wdv.z + hv.w * wdv.w;
    float ps = hv.x * wsv.x + hv.y * wsv.y + hv.z * wsv.z + hv.w * wsv.w;

    #pragma unroll
    for (int off = 16; off > 0; off >>= 1) {
        pd += __shfl_xor_sync(0xFFFFFFFF, pd, off);
        ps += __shfl_xor_sync(0xFFFFFFFF, ps, off);
    }
    if (lane == 0) {
        float dn = dnorm[warp];
        g_pd2[warp] = make_float2(pd, dn);
        g_ps2[warp] = make_float2(ps, dn);
    }
}

// ----------------------------------------------------- scan A: block sums
__global__ void scanA_kernel(int n_nodes) {
    __shared__ int red[SCAN_B];
    int t = threadIdx.x;
    int i = blockIdx.x * SCAN_B + t;
    red[t] = (i < n_nodes) ? g_deg[i] : 0;
    __syncthreads();
    #pragma unroll
    for (int off = SCAN_B / 2; off > 0; off >>= 1) {
        if (t < off) red[t] += red[t + off];
        __syncthreads();
    }
    if (t == 0) g_bsum[blockIdx.x] = red[0];
}

// ------------------------------------- scan B: one-warp scan of block sums
__global__ void scanB_kernel(int n_blocks, int n_nodes, int n_edges) {
    int lane = threadIdx.x;
    int chunk = (n_blocks + 31) / 32;   // <= 8 for N<=131072
    int base = lane * chunk;

    int excl_local[8];
    int s = 0;
    for (int j = 0; j < chunk; j++) {
        int idx = base + j;
        int v = (idx < n_blocks && j < 8) ? g_bsum[idx] : 0;
        if (j < 8) excl_local[j] = s;
        s += v;
    }
    int run = s;
    #pragma unroll
    for (int off = 1; off < 32; off <<= 1) {
        int u = __shfl_up_sync(0xFFFFFFFF, run, off);
        if (lane >= off) run += u;
    }
    int excl = run - s;
    for (int j = 0; j < chunk && j < 8; j++) {
        int idx = base + j;
        if (idx < n_blocks) g_boff[idx] = excl + excl_local[j];
    }
    if (lane == 0) g_offs[n_nodes] = n_edges;
}

// ------------------------- scan C: block exclusive scan via warp shuffles
__global__ void scanC_kernel(int n_nodes) {
    __shared__ int wsum[SCAN_B / 32];     // 16 warp partials
    int t = threadIdx.x;
    int lane = t & 31;
    int wid = t >> 5;
    int i = blockIdx.x * SCAN_B + t;
    int v = (i < n_nodes) ? g_deg[i] : 0;

    // warp-level inclusive scan
    int x = v;
    #pragma unroll
    for (int off = 1; off < 32; off <<= 1) {
        int u = __shfl_up_sync(0xFFFFFFFF, x, off);
        if (lane >= off) x += u;
    }
    if (lane == 31) wsum[wid] = x;
    __syncthreads();

    // warp 0 scans the 16 partials (exclusive)
    if (wid == 0 && lane < SCAN_B / 32) {
        int w = wsum[lane];
        int y = w;
        #pragma unroll
        for (int off = 1; off < SCAN_B / 32; off <<= 1) {
            int u = __shfl_up_sync(0xFFFF, y, off);
            if (lane >= off) y += u;
        }
        wsum[lane] = y - w;   // exclusive
    }
    __syncthreads();

    if (i < n_nodes) {
        int excl = (x - v) + wsum[wid] + g_boff[blockIdx.x];
        g_offs[i] = excl;
        g_cursor[i] = excl;
    }
}

// ------------------- scatter: 4 edges/thread via vector loads (high MLP)
__global__ void scatter_kernel(const float4* __restrict__ yes_no4,
                               const float* __restrict__ gate_b,
                               const float* __restrict__ yes_w,
                               const float* __restrict__ no_w,
                               const int4* __restrict__ src4,
                               const int4* __restrict__ dst4,
                               int n_quads) {
    int q = blockIdx.x * blockDim.x + threadIdx.x;
    if (q >= n_quads) return;

    int4 s4 = src4[q];
    int4 t4 = dst4[q];
    float4 yn4 = yes_no4[q];
    float gb = gate_b[0];
    float yw = yes_w[0];
    float nw = no_w[0];

    // issue all 8 random loads before consuming (MLP = 8)
    float2 pdt0 = g_pd2[t4.x];
    float2 pdt1 = g_pd2[t4.y];
    float2 pdt2 = g_pd2[t4.z];
    float2 pdt3 = g_pd2[t4.w];
    float2 pss0 = g_ps2[s4.x];
    float2 pss1 = g_ps2[s4.y];
    float2 pss2 = g_ps2[s4.z];
    float2 pss3 = g_ps2[s4.w];

    float c0 = (tanhf(pdt0.x + pss0.x + gb) + tanhf(yn4.x * yw + (1.f - yn4.x) * nw)) * 0.5f * pdt0.y * pss0.y;
    float c1 = (tanhf(pdt1.x + pss1.x + gb) + tanhf(yn4.y * yw + (1.f - yn4.y) * nw)) * 0.5f * pdt1.y * pss1.y;
    float c2 = (tanhf(pdt2.x + pss2.x + gb) + tanhf(yn4.z * yw + (1.f - yn4.z) * nw)) * 0.5f * pdt2.y * pss2.y;
    float c3 = (tanhf(pdt3.x + pss3.x + gb) + tanhf(yn4.w * yw + (1.f - yn4.w) * nw)) * 0.5f * pdt3.y * pss3.y;

    int p0 = atomicAdd(&g_cursor[t4.x], 1);
    int p1 = atomicAdd(&g_cursor[t4.y], 1);
    int p2 = atomicAdd(&g_cursor[t4.z], 1);
    int p3 = atomicAdd(&g_cursor[t4.w], 1);

    g_pairs[p0] = ((long long)__float_as_int(c0) << 32) | (unsigned int)s4.x;
    g_pairs[p1] = ((long long)__float_as_int(c1) << 32) | (unsigned int)s4.y;
    g_pairs[p2] = ((long long)__float_as_int(c2) << 32) | (unsigned int)s4.z;
    g_pairs[p3] = ((long long)__float_as_int(c3) << 32) | (unsigned int)s4.w;
}

// tail edges (n_edges not divisible by 4)
__global__ void scatter_tail_kernel(const float* __restrict__ yes_no,
                                    const float* __restrict__ gate_b,
                                    const float* __restrict__ yes_w,
                                    const float* __restrict__ no_w,
                                    const int* __restrict__ src,
                                    const int* __restrict__ dst,
                                    int e_begin, int n_edges) {
    int e = e_begin + blockIdx.x * blockDim.x + threadIdx.x;
    if (e >= n_edges) return;
    int s = src[e];
    int t = dst[e];
    float2 pdt = g_pd2[t];
    float2 pss = g_ps2[s];
    float yn = yes_no[e];
    float g = tanhf(pdt.x + pss.x + gate_b[0]);
    float y = tanhf(yn * yes_w[0] + (1.0f - yn) * no_w[0]);
    float coef = (g + y) * 0.5f * pdt.y * pss.y;
    int pos = atomicAdd(&g_cursor[t], 1);
    g_pairs[pos] = ((long long)__float_as_int(coef) << 32) | (unsigned int)s;
}

// ---------------------------------------------------------------- gather
// 16 lanes per node (2 nodes per warp), unroll 4.
__device__ __forceinline__ void fma_row16(float acc[8], long long p, int sub) {
    int s = (int)(unsigned int)(p & 0xffffffffLL);
    float c = __int_as_float((int)(p >> 32));
    const uint4* row = reinterpret_cast<const uint4*>(g_h2) + (size_t)s * 16;
    uint4 raw = row[sub];
    float2 f0 = __half22float2(*reinterpret_cast<__half2*>(&raw.x));
    float2 f1 = __half22float2(*reinterpret_cast<__half2*>(&raw.y));
    float2 f2 = __half22float2(*reinterpret_cast<__half2*>(&raw.z));
    float2 f3 = __half22float2(*reinterpret_cast<__half2*>(&raw.w));
    acc[0] += f0.x * c; acc[1] += f0.y * c;
    acc[2] += f1.x * c; acc[3] += f1.y * c;
    acc[4] += f2.x * c; acc[5] += f2.y * c;
    acc[6] += f3.x * c; acc[7] += f3.y * c;
}

__global__ void gather_kernel(float* __restrict__ z, int n_nodes) {
    int gwarp = (blockIdx.x * blockDim.x + threadIdx.x) >> 5;
    int lane = threadIdx.x & 31;
    int half = lane >> 4;
    int sub = lane & 15;
    int node = gwarp * 2 + half;
    if (node >= n_nodes) return;

    int start = g_offs[node];
    int end = g_offs[node + 1];

    float acc[8] = {0.f, 0.f, 0.f, 0.f, 0.f, 0.f, 0.f, 0.f};

    int i = start;
    for (; i + 3 < end; i += 4) {
        long long p0 = g_pairs[i];
        long long p1 = g_pairs[i + 1];
        long long p2 = g_pairs[i + 2];
        long long p3 = g_pairs[i + 3];
        fma_row16(acc, p0, sub);
        fma_row16(acc, p1, sub);
        fma_row16(acc, p2, sub);
        fma_row16(acc, p3, sub);
    }
    for (; i < end; i++) {
        fma_row16(acc, g_pairs[i], sub);
    }

    float4* zrow = reinterpret_cast<float4*>(z + (size_t)node * D);
    zrow[sub * 2]     = make_float4(acc[0], acc[1], acc[2], acc[3]);
    zrow[sub * 2 + 1] = make_float4(acc[4], acc[5], acc[6], acc[7]);
}

extern "C" void kernel_launch(void* const* d_in, const int* in_sizes, int n_in,
                              void* d_out, int out_size) {
    const float* h       = (const float*)d_in[0];
    const float* dnorm   = (const float*)d_in[1];
    const float* yes_no  = (const float*)d_in[2];
    const float* gate_w  = (const float*)d_in[3];
    const float* gate_b  = (const float*)d_in[4];
    const float* yes_w   = (const float*)d_in[5];
    const float* no_w    = (const float*)d_in[6];
    const int* src       = (const int*)d_in[7];
    const int* dst       = (const int*)d_in[8];
    float* z = (float*)d_out;

    int n_nodes = in_sizes[1];
    int n_edges = in_sizes[2];
    int scan_blocks = (n_nodes + SCAN_B - 1) / SCAN_B;

    // zero histogram (symbol address of device global — no allocation)
    void* deg_ptr = nullptr;
    cudaGetSymbolAddress(&deg_ptr, g_deg);
    cudaMemsetAsync(deg_ptr, 0, (size_t)n_nodes * sizeof(int), 0);

    {   // proj + fp16 convert + fused histogram
        int blocks = (n_nodes + 7) / 8;
        proj_kernel<<<blocks, 256>>>(h, dnorm, gate_w, dst, n_nodes, n_edges);
    }
    scanA_kernel<<<scan_blocks, SCAN_B>>>(n_nodes);
    scanB_kernel<<<1, 32>>>(scan_blocks, n_nodes, n_edges);
    scanC_kernel<<<scan_blocks, SCAN_B>>>(n_nodes);
    {   // scatter: 4 edges per thread
        int n_quads = n_edges / 4;
        if (n_quads > 0) {
            int blocks = (n_quads + 255) / 256;
            scatter_kernel<<<blocks, 256>>>(
                (const float4*)yes_no, gate_b, yes_w, no_w,
                (const int4*)src, (const int4*)dst, n_quads);
        }
        int tail = n_edges - n_quads * 4;
        if (tail > 0) {
            scatter_tail_kernel<<<1, 32>>>(yes_no, gate_b, yes_w, no_w,
                                           src, dst, n_quads * 4, n_edges);
        }
    }
    {   // gather: 2 nodes/warp, 16 lanes per node
        int warps_needed = (n_nodes + 1) / 2;
        int blocks = (warps_needed + 7) / 8;
        gather_kernel<<<blocks, 256>>>(z, n_nodes);
    }
}

// round 9
// speedup vs baseline: 1.0313x; 1.0313x over previous
#include <cuda_runtime.h>
#include <cuda_fp16.h>

// FALayer, dst-bucketed:
//   memset(deg) -> proj(+fp16 copy, +fused dst histogram, +zero scan state)
//   -> scan (single-kernel decoupled lookback) -> scatter (1 edge/thread)
//   -> gather (16 lanes/node, unroll 4)
// Inputs: 0 h[N,128]f32  1 d[N]f32  2 yes_no[E]f32  3 gate_w[1,256]f32
//         4 gate_b[1]f32 5 yes_w f32 6 no_w f32  7 src[E]i32  8 dst[E]i32
// Output: z[N,128]f32

#define D 128
#define MAX_N 100352
#define MAX_E 1605632
#define SCAN_T 512
#define SCAN_K 8
#define SCAN_TILE (SCAN_T * SCAN_K)     // 4096 nodes per block
#define MAX_SCAN_BLOCKS 64

__device__ float2 g_pd2[MAX_N];            // (p_dst, d) per node
__device__ float2 g_ps2[MAX_N];            // (p_src, d) per node
__device__ int g_deg[MAX_N];
__device__ int g_offs[MAX_N + 1];
__device__ int g_cursor[MAX_N];
__device__ volatile unsigned long long g_state[MAX_SCAN_BLOCKS]; // hi32 flag, lo32 value
__device__ long long g_pairs[MAX_E];                 // lo32 src, hi32 coef bits
__device__ __half2 g_h2[(size_t)MAX_N * (D / 2)];    // fp16 h copy (25.7 MB)

// ---------------- proj + fp16 convert + fused dst histogram + state zero
__global__ void proj_kernel(const float* __restrict__ h,
                            const float* __restrict__ dnorm,
                            const float* __restrict__ gate_w,
                            const int* __restrict__ dst,
                            int n_nodes, int n_edges) {
    int gtid = blockIdx.x * blockDim.x + threadIdx.x;

    if (gtid < MAX_SCAN_BLOCKS) g_state[gtid] = 0ULL;   // reset lookback state

    // fused histogram (g_deg pre-zeroed by memset); grid covers all edges
    for (int e = gtid; e < n_edges; e += gridDim.x * blockDim.x)
        atomicAdd(&g_deg[dst[e]], 1);

    int warp = gtid >> 5;
    int lane = threadIdx.x & 31;
    if (warp >= n_nodes) return;

    const float4* hrow = reinterpret_cast<const float4*>(h + (size_t)warp * D);
    const float4* wd = reinterpret_cast<const float4*>(gate_w);
    const float4* ws = reinterpret_cast<const float4*>(gate_w + D);

    float4 hv = hrow[lane];
    float4 wdv = wd[lane];
    float4 wsv = ws[lane];

    __half2 a = __floats2half2_rn(hv.x, hv.y);
    __half2 b = __floats2half2_rn(hv.z, hv.w);
    size_t base = (size_t)warp * (D / 2) + lane * 2;
    g_h2[base] = a;
    g_h2[base + 1] = b;

    float pd = hv.x * wdv.x + hv.y * wdv.y + hv.z * wdv.z + hv.w * wdv.w;
    float ps = hv.x * wsv.x + hv.y * wsv.y + hv.z * wsv.z + hv.w * wsv.w;

    #pragma unroll
    for (int off = 16; off > 0; off >>= 1) {
        pd += __shfl_xor_sync(0xFFFFFFFF, pd, off);
        ps += __shfl_xor_sync(0xFFFFFFFF, ps, off);
    }
    if (lane == 0) {
        float dn = dnorm[warp];
        g_pd2[warp] = make_float2(pd, dn);
        g_ps2[warp] = make_float2(ps, dn);
    }
}

// --------------- single-kernel exclusive scan with decoupled lookback
__global__ void scan_kernel(int n_nodes, int n_edges) {
    __shared__ int wsum[SCAN_T / 32];
    __shared__ int round_total;
    __shared__ int block_base;

    int b = blockIdx.x;
    int t = threadIdx.x;
    int lane = t & 31;
    int wid = t >> 5;

    int excl[SCAN_K];
    int running = 0;

    #pragma unroll
    for (int k = 0; k < SCAN_K; k++) {
        int i = b * SCAN_TILE + k * SCAN_T + t;
        int v = (i < n_nodes) ? g_deg[i] : 0;

        // warp inclusive scan
        int x = v;
        #pragma unroll
        for (int off = 1; off < 32; off <<= 1) {
            int u = __shfl_up_sync(0xFFFFFFFF, x, off);
            if (lane >= off) x += u;
        }
        if (lane == 31) wsum[wid] = x;
        __syncthreads();

        if (wid == 0 && lane < SCAN_T / 32) {
            int w = wsum[lane];
            int y = w;
            #pragma unroll
            for (int off = 1; off < SCAN_T / 32; off <<= 1) {
                int u = __shfl_up_sync(0xFFFF, y, off);
                if (lane >= off) y += u;
            }
            wsum[lane] = y - w;                 // exclusive warp partials
            if (lane == SCAN_T / 32 - 1) round_total = y;
        }
        __syncthreads();

        excl[k] = (x - v) + wsum[wid] + running;
        running += round_total;
        __syncthreads();   // protect wsum/round_total before next round
    }

    // decoupled lookback (thread 0)
    if (t == 0) {
        if (b == 0) {
            g_state[0] = (2ULL << 32) | (unsigned int)running;  // inclusive
            block_base = 0;
        } else {
            g_state[b] = (1ULL << 32) | (unsigned int)running;  // aggregate
            int base = 0;
            int j = b - 1;
            while (true) {
                unsigned long long s;
                do { s = g_state[j]; } while ((s >> 32) == 0);
                base += (int)(unsigned int)s;
                if ((s >> 32) == 2ULL) break;
                j--;
            }
            g_state[b] = (2ULL << 32) | (unsigned int)(base + running);
            block_base = base;
        }
    }
    __syncthreads();

    int base = block_base;
    #pragma unroll
    for (int k = 0; k < SCAN_K; k++) {
        int i = b * SCAN_TILE + k * SCAN_T + t;
        if (i < n_nodes) {
            int e = excl[k] + base;
            g_offs[i] = e;
            g_cursor[i] = e;
        }
    }
    if (b == 0 && t == 0) g_offs[n_nodes] = n_edges;
}

// ------------------------- scatter: coef fully precomputed, 1 edge/thread
__global__ void scatter_kernel(const float* __restrict__ yes_no,
                               const float* __restrict__ gate_b,
                               const float* __restrict__ yes_w,
                               const float* __restrict__ no_w,
                               const int* __restrict__ src,
                               const int* __restrict__ dst,
                               int n_edges) {
    int e = blockIdx.x * blockDim.x + threadIdx.x;
    if (e >= n_edges) return;

    int s = src[e];
    int t = dst[e];

    float2 pdt = g_pd2[t];   // (p_dst[t], d[t])
    float2 pss = g_ps2[s];   // (p_src[s], d[s])

    float yn = yes_no[e];
    float g = tanhf(pdt.x + pss.x + gate_b[0]);
    float y = tanhf(yn * yes_w[0] + (1.0f - yn) * no_w[0]);
    float coef = (g + y) * 0.5f * pdt.y * pss.y;

    int pos = atomicAdd(&g_cursor[t], 1);
    long long packed = ((long long)__float_as_int(coef) << 32) | (unsigned int)s;
    g_pairs[pos] = packed;
}

// ---------------------------------------------------------------- gather
// 16 lanes per node (2 nodes per warp), unroll 4.
__device__ __forceinline__ void fma_row16(float acc[8], long long p, int sub) {
    int s = (int)(unsigned int)(p & 0xffffffffLL);
    float c = __int_as_float((int)(p >> 32));
    const uint4* row = reinterpret_cast<const uint4*>(g_h2) + (size_t)s * 16;
    uint4 raw = row[sub];
    float2 f0 = __half22float2(*reinterpret_cast<__half2*>(&raw.x));
    float2 f1 = __half22float2(*reinterpret_cast<__half2*>(&raw.y));
    float2 f2 = __half22float2(*reinterpret_cast<__half2*>(&raw.z));
    float2 f3 = __half22float2(*reinterpret_cast<__half2*>(&raw.w));
    acc[0] += f0.x * c; acc[1] += f0.y * c;
    acc[2] += f1.x * c; acc[3] += f1.y * c;
    acc[4] += f2.x * c; acc[5] += f2.y * c;
    acc[6] += f3.x * c; acc[7] += f3.y * c;
}

__global__ void gather_kernel(float* __restrict__ z, int n_nodes) {
    int gwarp = (blockIdx.x * blockDim.x + threadIdx.x) >> 5;
    int lane = threadIdx.x & 31;
    int half = lane >> 4;
    int sub = lane & 15;
    int node = gwarp * 2 + half;
    if (node >= n_nodes) return;

    int start = g_offs[node];
    int end = g_offs[node + 1];

    float acc[8] = {0.f, 0.f, 0.f, 0.f, 0.f, 0.f, 0.f, 0.f};

    int i = start;
    for (; i + 3 < end; i += 4) {
        long long p0 = g_pairs[i];
        long long p1 = g_pairs[i + 1];
        long long p2 = g_pairs[i + 2];
        long long p3 = g_pairs[i + 3];
        fma_row16(acc, p0, sub);
        fma_row16(acc, p1, sub);
        fma_row16(acc, p2, sub);
        fma_row16(acc, p3, sub);
    }
    for (; i < end; i++) {
        fma_row16(acc, g_pairs[i], sub);
    }

    float4* zrow = reinterpret_cast<float4*>(z + (size_t)node * D);
    zrow[sub * 2]     = make_float4(acc[0], acc[1], acc[2], acc[3]);
    zrow[sub * 2 + 1] = make_float4(acc[4], acc[5], acc[6], acc[7]);
}

extern "C" void kernel_launch(void* const* d_in, const int* in_sizes, int n_in,
                              void* d_out, int out_size) {
    const float* h       = (const float*)d_in[0];
    const float* dnorm   = (const float*)d_in[1];
    const float* yes_no  = (const float*)d_in[2];
    const float* gate_w  = (const float*)d_in[3];
    const float* gate_b  = (const float*)d_in[4];
    const float* yes_w   = (const float*)d_in[5];
    const float* no_w    = (const float*)d_in[6];
    const int* src       = (const int*)d_in[7];
    const int* dst       = (const int*)d_in[8];
    float* z = (float*)d_out;

    int n_nodes = in_sizes[1];
    int n_edges = in_sizes[2];
    int scan_blocks = (n_nodes + SCAN_TILE - 1) / SCAN_TILE;   // 25 for N=100000

    // zero histogram (symbol address of device global — no allocation)
    void* deg_ptr = nullptr;
    cudaGetSymbolAddress(&deg_ptr, g_deg);
    cudaMemsetAsync(deg_ptr, 0, (size_t)n_nodes * sizeof(int), 0);

    {   // proj + fp16 convert + fused histogram + scan-state reset
        int blocks = (n_nodes + 7) / 8;
        proj_kernel<<<blocks, 256>>>(h, dnorm, gate_w, dst, n_nodes, n_edges);
    }
    // single-kernel exclusive scan (decoupled lookback)
    scan_kernel<<<scan_blocks, SCAN_T>>>(n_nodes, n_edges);
    {   // scatter with precomputed coefficients
        int blocks = (n_edges + 255) / 256;
        scatter_kernel<<<blocks, 256>>>(yes_no, gate_b, yes_w, no_w,
                                        src, dst, n_edges);
    }
    {   // gather: 2 nodes/warp, 16 lanes per node
        int warps_needed = (n_nodes + 1) / 2;
        int blocks = (warps_needed + 7) / 8;
        gather_kernel<<<blocks, 256>>>(z, n_nodes);
    }
}